// round 13
// baseline (speedup 1.0000x reference)
#include <cuda_runtime.h>
#include <cuda_bf16.h>
#include <cstdint>
#include <cstddef>

#define BB 24
#define DD 128
#define NN 2048
#define MM 2048
#define KB 32
#define T_WORDS 2048

__device__ float g_S [(size_t)BB * NN * MM];
__device__ float g_A [(size_t)BB * DD * NN];
__device__ float g_Bt[(size_t)BB * DD * NN];
__device__ float g_L1[BB * NN];
__device__ float g_L2[BB * MM];
__device__ float g_sq[BB * MM];
__device__ float g_sc[BB * NN];
__device__ float2 g_rowp[(size_t)BB * 16 * NN];
__device__ float2 g_colp[(size_t)BB * 16 * MM];
__device__ __nv_bfloat16 g_Chi[(size_t)BB * DD * NN];
__device__ __nv_bfloat16 g_Clo[(size_t)BB * DD * NN];
__device__ __nv_bfloat16 g_Qhi[(size_t)BB * DD * MM];
__device__ __nv_bfloat16 g_Qlo[(size_t)BB * DD * MM];
__device__ __nv_bfloat16 g_CBhi[(size_t)BB * DD * MM];
__device__ __nv_bfloat16 g_CBlo[(size_t)BB * DD * MM];
__device__ __nv_bfloat16 g_CThi[(size_t)BB * NN * DD];
__device__ __nv_bfloat16 g_CTlo[(size_t)BB * NN * DD];
__device__ __nv_bfloat16 g_QWhi[(size_t)BB * MM * DD];
__device__ __nv_bfloat16 g_QWlo[(size_t)BB * MM * DD];

// ---- warp mma + ldmatrix ----
__device__ __forceinline__ void mma16816(float* c, const uint32_t* a, const uint32_t* b) {
    asm volatile("mma.sync.aligned.m16n8k16.row.col.f32.bf16.bf16.f32 "
                 "{%0,%1,%2,%3},{%4,%5,%6,%7},{%8,%9},{%0,%1,%2,%3};"
                 : "+f"(c[0]), "+f"(c[1]), "+f"(c[2]), "+f"(c[3])
                 : "r"(a[0]), "r"(a[1]), "r"(a[2]), "r"(a[3]), "r"(b[0]), "r"(b[1]));
}
__device__ __forceinline__ void ldsm4(uint32_t* r, uint32_t saddr) {
    asm volatile("ldmatrix.sync.aligned.m8n8.x4.shared.b16 {%0,%1,%2,%3}, [%4];"
                 : "=r"(r[0]), "=r"(r[1]), "=r"(r[2]), "=r"(r[3]) : "r"(saddr));
}
__device__ __forceinline__ uint32_t su32(const void* p) { return (uint32_t)__cvta_generic_to_shared(p); }

__device__ __forceinline__ void splitf(float x, uint16_t& h, uint16_t& l) {
    __nv_bfloat16 bh = __float2bfloat16_rn(x);
    float r = x - __bfloat162float(bh);
    __nv_bfloat16 bl = __float2bfloat16_rn(r);
    h = __bfloat16_as_ushort(bh); l = __bfloat16_as_ushort(bl);
}
__device__ __forceinline__ uint32_t packsplit_hi(float a, float b) {
    uint16_t h0, l0, h1, l1; splitf(a, h0, l0); splitf(b, h1, l1);
    return (uint32_t)h0 | ((uint32_t)h1 << 16);
}
__device__ __forceinline__ uint32_t packsplit_lo(float a, float b) {
    uint16_t h0, l0, h1, l1; splitf(a, h0, l0); splitf(b, h1, l1);
    return (uint32_t)l0 | ((uint32_t)l1 << 16);
}
// fast exp on FMA pipe (rel err ~2.4e-6)
__device__ __forceinline__ float fexp(float x) {
    float t = fmaxf(x * 1.4426950408889634f, -126.0f);
    float kf = t + 12582912.0f;
    float fi = kf - 12582912.0f;
    float f = t - fi;
    float p = 1.3333558146e-3f;
    p = fmaf(p, f, 9.6181291076e-3f);
    p = fmaf(p, f, 5.5504108665e-2f);
    p = fmaf(p, f, 2.4022650696e-1f);
    p = fmaf(p, f, 6.9314718056e-1f);
    p = fmaf(p, f, 1.0f);
    return __int_as_float(__float_as_int(p) + (((int)fi) << 23));
}

// ---- threefry2x32, JAX partitionable, key=(0,42) ----
__device__ __forceinline__ uint32_t rotl32(uint32_t x, int r) { return __funnelshift_l(x, x, r); }
#define TF_ROUND4(a, b, c, d)                       \
    x0 += x1; x1 = rotl32(x1, a); x1 ^= x0;         \
    x0 += x1; x1 = rotl32(x1, b); x1 ^= x0;         \
    x0 += x1; x1 = rotl32(x1, c); x1 ^= x0;         \
    x0 += x1; x1 = rotl32(x1, d); x1 ^= x0;
__device__ __forceinline__ uint32_t threefry_bits(uint32_t idx) {
    const uint32_t ks0 = 0u, ks1 = 42u;
    const uint32_t ks2 = 0x1BD11BDAu ^ ks0 ^ ks1;
    uint32_t x0 = 0u + ks0, x1 = idx + ks1;
    TF_ROUND4(13, 15, 26, 6)  x0 += ks1; x1 += ks2 + 1u;
    TF_ROUND4(17, 29, 16, 24) x0 += ks2; x1 += ks0 + 2u;
    TF_ROUND4(13, 15, 26, 6)  x0 += ks0; x1 += ks1 + 3u;
    TF_ROUND4(17, 29, 16, 24) x0 += ks1; x1 += ks2 + 4u;
    TF_ROUND4(13, 15, 26, 6)  x0 += ks2; x1 += ks0 + 5u;
    return x0 ^ x1;
}
__device__ __forceinline__ float dropscale(uint32_t idx, float v) {
    uint32_t bits = threefry_bits(idx);
    float u = __uint_as_float((bits >> 9) | 0x3f800000u) - 1.0f;
    return (u < 0.9f) ? v * (1.0f / 0.9f) : 0.0f;
}

// ---- stage 0: biases ----
__global__ __launch_bounds__(256) void bias_kernel(const float* __restrict__ C,
                                                   const float* __restrict__ Q,
                                                   const float* __restrict__ W) {
    int b = blockIdx.y;
    int m = blockIdx.x * 256 + threadIdx.x;
    const float* X; const float* wv; float* out;
    if (blockIdx.z == 0) { X = Q + (size_t)b * DD * MM; wv = W + b * 3 * DD;      out = g_sq + b * MM; }
    else                 { X = C + (size_t)b * DD * NN; wv = W + b * 3 * DD + DD; out = g_sc + b * NN; }
    __shared__ float ws[DD];
    if (threadIdx.x < DD) ws[threadIdx.x] = wv[threadIdx.x];
    __syncthreads();
    float acc = 0.0f;
#pragma unroll 8
    for (int d = 0; d < DD; d++) acc = fmaf(ws[d], X[(size_t)d * MM + m], acc);
    out[m] = acc;
}

// ---- stage 0b: split C,Q in [d][*] layout ----
__global__ __launch_bounds__(256) void split_cq_kernel(const float* __restrict__ C,
                                                       const float* __restrict__ Q) {
    size_t i = ((size_t)blockIdx.x * 256 + threadIdx.x) * 4;
    const float* src; __nv_bfloat16 *dh, *dl;
    if (blockIdx.y == 0) { src = C; dh = g_Chi; dl = g_Clo; }
    else                 { src = Q; dh = g_Qhi; dl = g_Qlo; }
    float4 v = *(const float4*)(src + i);
    *(uint2*)(dh + i) = make_uint2(packsplit_hi(v.x, v.y), packsplit_hi(v.z, v.w));
    *(uint2*)(dl + i) = make_uint2(packsplit_lo(v.x, v.y), packsplit_lo(v.z, v.w));
}

// ---- stage 0c: transpose-split for s_mma ----
__global__ __launch_bounds__(256) void tsplit_kernel(const float* __restrict__ C,
                                                     const float* __restrict__ Q,
                                                     const float* __restrict__ W) {
    __shared__ float ts[32][33];
    __shared__ float wsc[32];
    int z = blockIdx.z, b = z >> 1, isQ = z & 1;
    int n0 = blockIdx.x * 32, d0 = blockIdx.y * 32;
    const float* X = (isQ ? Q : C) + (size_t)b * DD * NN;
    int t = threadIdx.x, nl = t & 31, dr = t >> 5;
    if (t < 32) wsc[t] = isQ ? W[b * 3 * DD + 2 * DD + d0 + t] : 1.0f;
#pragma unroll
    for (int k = 0; k < 4; k++)
        ts[dr + k * 8][nl] = X[(size_t)(d0 + dr + k * 8) * NN + n0 + nl];
    __syncthreads();
    int nr = t >> 3, dg = (t & 7) * 4;
    __nv_bfloat16* dh = (isQ ? g_QWhi : g_CThi) + ((size_t)b * NN + n0 + nr) * DD + d0 + dg;
    __nv_bfloat16* dl = (isQ ? g_QWlo : g_CTlo) + ((size_t)b * NN + n0 + nr) * DD + d0 + dg;
    float v0 = ts[dg][nr] * wsc[dg],     v1 = ts[dg + 1][nr] * wsc[dg + 1];
    float v2 = ts[dg + 2][nr] * wsc[dg + 2], v3 = ts[dg + 3][nr] * wsc[dg + 3];
    *(uint2*)dh = make_uint2(packsplit_hi(v0, v1), packsplit_hi(v2, v3));
    *(uint2*)dl = make_uint2(packsplit_lo(v0, v1), packsplit_lo(v2, v3));
}

// ---- stage 1: S via HMMA, 2 sub-tiles per barrier ----
#define G1_SMEM (1024 + 8 * 8192)
__global__ __launch_bounds__(256) void s_mma() {
    extern __shared__ char smc[];
    float* sc_s = (float*)smc;
    float* sq_s = (float*)(smc + 512);
    char* tiles = smc + 1024;   // AH[2],AL[2],BH[2],BL[2] each 8KB: layout [op][sub]
    float* st  = (float*)(smc + 1024);
    float* rm4 = st;
    float* rfin = st + 512;
    float* rs4 = st + 640;
    float* cm2 = st + 1152;
    float* cfin = st + 1408;
    float* cs2 = st + 1536;
    int tid = threadIdx.x, lane = tid & 31, wid = tid >> 5;
    int b = blockIdx.z, n0 = blockIdx.y * 128, m0 = blockIdx.x * 128;
    if (tid < 128) { sc_s[tid] = g_sc[b * NN + n0 + tid]; sq_s[tid] = g_sq[b * MM + m0 + tid]; }
    const __nv_bfloat16* Ahg = g_CThi + ((size_t)b * NN + n0) * DD;
    const __nv_bfloat16* Alg = g_CTlo + ((size_t)b * NN + n0) * DD;
    const __nv_bfloat16* Bhg = g_QWhi + ((size_t)b * MM + m0) * DD;
    const __nv_bfloat16* Blg = g_QWlo + ((size_t)b * MM + m0) * DD;
    int wm = (wid & 1) * 64, wn = (wid >> 1) * 32;
    int g = lane >> 2, t4 = lane & 3;
    int arow = lane & 15, achk = lane >> 4, aswz = (arow >> 1) & 3;
    int brow = lane & 7, bsel = (lane >> 4) & 1, bchk = (lane >> 3) & 1, bswz = (brow >> 1) & 3;
    uint32_t sbase = su32(tiles);
    float acc[4][4][4] = {};
    int ar = tid >> 1, ac = (tid & 1) * 2, asw = (ar >> 1) & 3;
    __syncthreads();
    for (int it = 0; it < 2; it++) {
#pragma unroll
        for (int sub = 0; sub < 2; sub++) {
            int c = it * 2 + sub;
            uint4* AH = (uint4*)(tiles + (0 * 2 + sub) * 8192);
            uint4* AL = (uint4*)(tiles + (1 * 2 + sub) * 8192);
            uint4* BH = (uint4*)(tiles + (2 * 2 + sub) * 8192);
            uint4* BL = (uint4*)(tiles + (3 * 2 + sub) * 8192);
            const uint4* pah = (const uint4*)(Ahg + (size_t)ar * DD + c * 32);
            const uint4* pal = (const uint4*)(Alg + (size_t)ar * DD + c * 32);
            const uint4* pbh = (const uint4*)(Bhg + (size_t)ar * DD + c * 32);
            const uint4* pbl = (const uint4*)(Blg + (size_t)ar * DD + c * 32);
            AH[ar * 4 + (ac ^ asw)]       = pah[ac];
            AH[ar * 4 + ((ac + 1) ^ asw)] = pah[ac + 1];
            AL[ar * 4 + (ac ^ asw)]       = pal[ac];
            AL[ar * 4 + ((ac + 1) ^ asw)] = pal[ac + 1];
            BH[ar * 4 + (ac ^ asw)]       = pbh[ac];
            BH[ar * 4 + ((ac + 1) ^ asw)] = pbh[ac + 1];
            BL[ar * 4 + (ac ^ asw)]       = pbl[ac];
            BL[ar * 4 + ((ac + 1) ^ asw)] = pbl[ac + 1];
        }
        __syncthreads();
#pragma unroll
        for (int sub = 0; sub < 2; sub++) {
            uint32_t shAH = sbase + (0 * 2 + sub) * 8192;
            uint32_t shAL = sbase + (1 * 2 + sub) * 8192;
            uint32_t shBH = sbase + (2 * 2 + sub) * 8192;
            uint32_t shBL = sbase + (3 * 2 + sub) * 8192;
#pragma unroll
            for (int ks = 0; ks < 2; ks++) {
                uint32_t bh[4][2], bl[4][2];
#pragma unroll
                for (int p = 0; p < 2; p++) {
                    int j = wn + (2 * p + bsel) * 8 + brow;
                    uint32_t off = (uint32_t)(j * 16 + (((ks * 2 + bchk) ^ bswz) << 2)) * 4;
                    uint32_t r[4];
                    ldsm4(r, shBH + off);
                    bh[2 * p][0] = r[0]; bh[2 * p][1] = r[1];
                    bh[2 * p + 1][0] = r[2]; bh[2 * p + 1][1] = r[3];
                    ldsm4(r, shBL + off);
                    bl[2 * p][0] = r[0]; bl[2 * p][1] = r[1];
                    bl[2 * p + 1][0] = r[2]; bl[2 * p + 1][1] = r[3];
                }
#pragma unroll
                for (int mt = 0; mt < 4; mt++) {
                    int row = wm + mt * 16 + arow;
                    uint32_t off = (uint32_t)(row * 16 + (((ks * 2 + achk) ^ aswz) << 2)) * 4;
                    uint32_t ah[4], al[4];
                    ldsm4(ah, shAH + off);
                    ldsm4(al, shAL + off);
#pragma unroll
                    for (int nt = 0; nt < 4; nt++) {
                        mma16816(acc[mt][nt], ah, bh[nt]);
                        mma16816(acc[mt][nt], ah, bl[nt]);
                        mma16816(acc[mt][nt], al, bh[nt]);
                    }
                }
            }
        }
        __syncthreads();
    }
    float* Sb = g_S + (size_t)b * NN * MM;
#pragma unroll
    for (int mt = 0; mt < 4; mt++) {
#pragma unroll
        for (int nt = 0; nt < 4; nt++) {
            int r0 = wm + mt * 16 + g, c0 = wn + nt * 8 + t4 * 2;
            acc[mt][nt][0] += sc_s[r0] + sq_s[c0];
            acc[mt][nt][1] += sc_s[r0] + sq_s[c0 + 1];
            acc[mt][nt][2] += sc_s[r0 + 8] + sq_s[c0];
            acc[mt][nt][3] += sc_s[r0 + 8] + sq_s[c0 + 1];
            *(float2*)(Sb + (size_t)(n0 + r0) * MM + m0 + c0)     = make_float2(acc[mt][nt][0], acc[mt][nt][1]);
            *(float2*)(Sb + (size_t)(n0 + r0 + 8) * MM + m0 + c0) = make_float2(acc[mt][nt][2], acc[mt][nt][3]);
        }
    }
#pragma unroll
    for (int mt = 0; mt < 4; mt++) {
#pragma unroll
        for (int h = 0; h < 2; h++) {
            float m = acc[mt][0][h * 2];
#pragma unroll
            for (int nt = 0; nt < 4; nt++) {
                m = fmaxf(m, acc[mt][nt][h * 2]);
                m = fmaxf(m, acc[mt][nt][h * 2 + 1]);
            }
            m = fmaxf(m, __shfl_xor_sync(0xffffffffu, m, 1));
            m = fmaxf(m, __shfl_xor_sync(0xffffffffu, m, 2));
            if (t4 == 0) rm4[(wid >> 1) * 128 + wm + mt * 16 + g + 8 * h] = m;
        }
    }
    __syncthreads();
    if (tid < 128)
        rfin[tid] = fmaxf(fmaxf(rm4[tid], rm4[128 + tid]), fmaxf(rm4[256 + tid], rm4[384 + tid]));
    __syncthreads();
#pragma unroll
    for (int mt = 0; mt < 4; mt++) {
#pragma unroll
        for (int h = 0; h < 2; h++) {
            int r = wm + mt * 16 + g + 8 * h;
            float L = rfin[r], s = 0.0f;
#pragma unroll
            for (int nt = 0; nt < 4; nt++)
                s += fexp(acc[mt][nt][h * 2] - L) + fexp(acc[mt][nt][h * 2 + 1] - L);
            s += __shfl_xor_sync(0xffffffffu, s, 1);
            s += __shfl_xor_sync(0xffffffffu, s, 2);
            if (t4 == 0) rs4[(wid >> 1) * 128 + r] = s;
        }
    }
    __syncthreads();
    if (tid < 128)
        g_rowp[((size_t)(b * 16 + (m0 >> 7))) * NN + n0 + tid] =
            make_float2(rfin[tid], rs4[tid] + rs4[128 + tid] + rs4[256 + tid] + rs4[384 + tid]);
#pragma unroll
    for (int nt = 0; nt < 4; nt++) {
#pragma unroll
        for (int e = 0; e < 2; e++) {
            float m = acc[0][nt][e];
#pragma unroll
            for (int mt = 0; mt < 4; mt++) {
                m = fmaxf(m, acc[mt][nt][e]);
                m = fmaxf(m, acc[mt][nt][2 + e]);
            }
            m = fmaxf(m, __shfl_xor_sync(0xffffffffu, m, 4));
            m = fmaxf(m, __shfl_xor_sync(0xffffffffu, m, 8));
            m = fmaxf(m, __shfl_xor_sync(0xffffffffu, m, 16));
            if (g == 0) cm2[(wid & 1) * 128 + wn + nt * 8 + t4 * 2 + e] = m;
        }
    }
    __syncthreads();
    if (tid < 128) cfin[tid] = fmaxf(cm2[tid], cm2[128 + tid]);
    __syncthreads();
#pragma unroll
    for (int nt = 0; nt < 4; nt++) {
#pragma unroll
        for (int e = 0; e < 2; e++) {
            int c = wn + nt * 8 + t4 * 2 + e;
            float L = cfin[c], s = 0.0f;
#pragma unroll
            for (int mt = 0; mt < 4; mt++)
                s += fexp(acc[mt][nt][e] - L) + fexp(acc[mt][nt][2 + e] - L);
            s += __shfl_xor_sync(0xffffffffu, s, 4);
            s += __shfl_xor_sync(0xffffffffu, s, 8);
            s += __shfl_xor_sync(0xffffffffu, s, 16);
            if (g == 0) cs2[(wid & 1) * 128 + c] = s;
        }
    }
    __syncthreads();
    if (tid < 128)
        g_colp[((size_t)(b * 16 + (n0 >> 7))) * MM + m0 + tid] =
            make_float2(cfin[tid], cs2[tid] + cs2[128 + tid]);
}

// ---- stage 2: combines ----
__global__ __launch_bounds__(256) void rowcombine_kernel() {
    int idx = blockIdx.x * 256 + threadIdx.x;
    int b = idx >> 11, n = idx & (NN - 1);
    const float2* p = g_rowp + (size_t)(b * 16) * NN + n;
    float2 f = p[0]; float mx = f.x, s = f.y;
#pragma unroll
    for (int t = 1; t < 16; t++) {
        float2 g = p[(size_t)t * NN];
        float nm = fmaxf(mx, g.x);
        s = s * __expf(mx - nm) + g.y * __expf(g.x - nm); mx = nm;
    }
    g_L1[idx] = mx + logf(s);
}
__global__ __launch_bounds__(256) void colcombine_kernel() {
    int idx = blockIdx.x * 256 + threadIdx.x;
    int b = idx >> 11, m = idx & (MM - 1);
    const float2* p = g_colp + (size_t)(b * 16) * MM + m;
    float2 f = p[0]; float mx = f.x, s = f.y;
#pragma unroll
    for (int t = 1; t < 16; t++) {
        float2 g = p[(size_t)t * MM];
        float nm = fmaxf(mx, g.x);
        s = s * __expf(mx - nm) + g.y * __expf(g.x - nm); mx = nm;
    }
    g_L2[idx] = mx + logf(s);
}

// ---- stage 3: CB = C * E2 via HMMA (R11 single-buffer) ----
__global__ __launch_bounds__(256) void cb_mma() {
    extern __shared__ char smc[];
    float* l2s = (float*)smc;
    uint32_t* AH = (uint32_t*)(smc + 512);
    uint32_t* AL = AH + T_WORDS;
    uint32_t* EH = AL + T_WORDS;
    uint32_t* EL = EH + T_WORDS;
    int tid = threadIdx.x, lane = tid & 31, wid = tid >> 5;
    int b = blockIdx.y, m0 = blockIdx.x * 128;
    if (tid < 128) l2s[tid] = g_L2[b * MM + m0 + tid];
    const float* Sb = g_S + (size_t)b * NN * MM;
    const __nv_bfloat16* Ch = g_Chi + (size_t)b * DD * NN;
    const __nv_bfloat16* Cl = g_Clo + (size_t)b * DD * NN;
    int wm = (wid & 1) * 64, wn = (wid >> 1) * 32;
    int g = lane >> 2, t4 = lane & 3;
    int arow = lane & 15, achk = lane >> 4, aswz = (arow >> 1) & 3;
    int brow = lane & 7, bsel = (lane >> 4) & 1, bchk = (lane >> 3) & 1, bswz = (brow >> 1) & 3;
    uint32_t shAH = su32(AH), shAL = su32(AL), shEH = su32(EH), shEL = su32(EL);
    float acc[4][4][4] = {};
    int ar = tid >> 1, ac = (tid & 1) * 2, asw = (ar >> 1) & 3;
    int kp = tid & 15, mb = tid >> 4;
    __syncthreads();
    for (int c = 0; c < NN / KB; c++) {
        int n0 = c * KB;
        {
            const uint4* ph = (const uint4*)(Ch + (size_t)ar * NN + n0);
            const uint4* pl = (const uint4*)(Cl + (size_t)ar * NN + n0);
            ((uint4*)AH)[ar * 4 + (ac ^ asw)]       = ph[ac];
            ((uint4*)AH)[ar * 4 + ((ac + 1) ^ asw)] = ph[ac + 1];
            ((uint4*)AL)[ar * 4 + (ac ^ asw)]       = pl[ac];
            ((uint4*)AL)[ar * 4 + ((ac + 1) ^ asw)] = pl[ac + 1];
        }
        {
            const float* s0 = Sb + (size_t)(n0 + 2 * kp) * MM + m0 + mb * 8;
            const float* s1 = s0 + MM;
            float4 x0 = *(const float4*)s0, x1 = *(const float4*)(s0 + 4);
            float4 y0 = *(const float4*)s1, y1 = *(const float4*)(s1 + 4);
            float xs[8] = {x0.x, x0.y, x0.z, x0.w, x1.x, x1.y, x1.z, x1.w};
            float ys[8] = {y0.x, y0.y, y0.z, y0.w, y1.x, y1.y, y1.z, y1.w};
#pragma unroll
            for (int i = 0; i < 8; i++) {
                int m = mb * 8 + i;
                float L = l2s[m];
                float e0 = fexp(xs[i] - L), e1 = fexp(ys[i] - L);
                int w = m * 16 + (kp ^ (((m >> 1) & 3) << 2));
                EH[w] = packsplit_hi(e0, e1);
                EL[w] = packsplit_lo(e0, e1);
            }
        }
        __syncthreads();
#pragma unroll
        for (int ks = 0; ks < 2; ks++) {
            uint32_t bh[4][2], bl[4][2];
#pragma unroll
            for (int p = 0; p < 2; p++) {
                int j = wn + (2 * p + bsel) * 8 + brow;
                uint32_t off = (uint32_t)(j * 16 + (((ks * 2 + bchk) ^ bswz) << 2)) * 4;
                uint32_t r[4];
                ldsm4(r, shEH + off);
                bh[2 * p][0] = r[0]; bh[2 * p][1] = r[1];
                bh[2 * p + 1][0] = r[2]; bh[2 * p + 1][1] = r[3];
                ldsm4(r, shEL + off);
                bl[2 * p][0] = r[0]; bl[2 * p][1] = r[1];
                bl[2 * p + 1][0] = r[2]; bl[2 * p + 1][1] = r[3];
            }
#pragma unroll
            for (int mt = 0; mt < 4; mt++) {
                int row = wm + mt * 16 + arow;
                uint32_t off = (uint32_t)(row * 16 + (((ks * 2 + achk) ^ aswz) << 2)) * 4;
                uint32_t ah[4], al[4];
                ldsm4(ah, shAH + off);
                ldsm4(al, shAL + off);
#pragma unroll
                for (int nt = 0; nt < 4; nt++) {
                    mma16816(acc[mt][nt], ah, bh[nt]);
                    mma16816(acc[mt][nt], ah, bl[nt]);
                    mma16816(acc[mt][nt], al, bh[nt]);
                }
            }
        }
        __syncthreads();
    }
#pragma unroll
    for (int mt = 0; mt < 4; mt++) {
#pragma unroll
        for (int nt = 0; nt < 4; nt++) {
            float* cfr = acc[mt][nt];
            int d0 = wm + mt * 16 + g;
            int col = m0 + wn + nt * 8 + t4 * 2;
            size_t o0 = (size_t)(b * DD + d0) * MM + col;
            size_t o1 = (size_t)(b * DD + d0 + 8) * MM + col;
            *(uint32_t*)(g_CBhi + o0) = packsplit_hi(cfr[0], cfr[1]);
            *(uint32_t*)(g_CBlo + o0) = packsplit_lo(cfr[0], cfr[1]);
            *(uint32_t*)(g_CBhi + o1) = packsplit_hi(cfr[2], cfr[3]);
            *(uint32_t*)(g_CBlo + o1) = packsplit_lo(cfr[2], cfr[3]);
        }
    }
}

// ---- stage 4: fused A + Bt (R11 single-buffer) ----
#define ABF_SMEM (512 + 4 * 8192 + 2 * 4096)
__global__ __launch_bounds__(256) void abf_mma() {
    extern __shared__ char smc[];
    float* l1s = (float*)smc;
    uint32_t* QH = (uint32_t*)(smc + 512);
    uint32_t* QL = QH + 2048;
    uint32_t* BH = QL + 2048;
    uint32_t* BL = BH + 2048;
    uint32_t* EH = BL + 2048;
    uint32_t* EL = EH + 1024;
    int tid = threadIdx.x, lane = tid & 31, wid = tid >> 5;
    int b = blockIdx.y, n0 = blockIdx.x * 64;
    if (tid < 64) l1s[tid] = g_L1[b * NN + n0 + tid];
    const float* Sb = g_S + (size_t)b * NN * MM;
    const __nv_bfloat16* Qh = g_Qhi + (size_t)b * DD * MM;
    const __nv_bfloat16* Ql = g_Qlo + (size_t)b * DD * MM;
    const __nv_bfloat16* Bh = g_CBhi + (size_t)b * DD * MM;
    const __nv_bfloat16* Bl = g_CBlo + (size_t)b * DD * MM;
    int isBt = wid >> 2, wg = wid & 3;
    int wm = (wg & 1) * 64, wn = (wg >> 1) * 32;
    int g = lane >> 2, t4 = lane & 3;
    int arow = lane & 15, achk = lane >> 4, aswz = (arow >> 1) & 3;
    int brow = lane & 7, bsel = (lane >> 4) & 1, bchk = (lane >> 3) & 1, bswz = (brow >> 1) & 3;
    uint32_t shXH = isBt ? su32(BH) : su32(QH);
    uint32_t shXL = isBt ? su32(BL) : su32(QL);
    uint32_t shEH = su32(EH), shEL = su32(EL);
    float acc[4][4][4] = {};
    int ar = tid >> 1, ac = (tid & 1) * 2, asw = (ar >> 1) & 3;
    int nr = tid >> 2, q4 = tid & 3;
    __syncthreads();
    for (int c = 0; c < MM / KB; c++) {
        int mc0 = c * KB;
        {
            const uint4* pqh = (const uint4*)(Qh + (size_t)ar * MM + mc0);
            const uint4* pql = (const uint4*)(Ql + (size_t)ar * MM + mc0);
            const uint4* pbh = (const uint4*)(Bh + (size_t)ar * MM + mc0);
            const uint4* pbl = (const uint4*)(Bl + (size_t)ar * MM + mc0);
            ((uint4*)QH)[ar * 4 + (ac ^ asw)]       = pqh[ac];
            ((uint4*)QH)[ar * 4 + ((ac + 1) ^ asw)] = pqh[ac + 1];
            ((uint4*)QL)[ar * 4 + (ac ^ asw)]       = pql[ac];
            ((uint4*)QL)[ar * 4 + ((ac + 1) ^ asw)] = pql[ac + 1];
            ((uint4*)BH)[ar * 4 + (ac ^ asw)]       = pbh[ac];
            ((uint4*)BH)[ar * 4 + ((ac + 1) ^ asw)] = pbh[ac + 1];
            ((uint4*)BL)[ar * 4 + (ac ^ asw)]       = pbl[ac];
            ((uint4*)BL)[ar * 4 + ((ac + 1) ^ asw)] = pbl[ac + 1];
        }
        {
            const float* sp = Sb + (size_t)(n0 + nr) * MM + mc0 + q4 * 8;
            float4 v0 = *(const float4*)sp, v1 = *(const float4*)(sp + 4);
            float vs[8] = {v0.x, v0.y, v0.z, v0.w, v1.x, v1.y, v1.z, v1.w};
            float L = l1s[nr];
            int sn = ((nr >> 1) & 3) << 2;
#pragma unroll
            for (int j = 0; j < 4; j++) {
                float e0 = fexp(vs[2 * j] - L), e1 = fexp(vs[2 * j + 1] - L);
                int w = nr * 16 + ((q4 * 4 + j) ^ sn);
                EH[w] = packsplit_hi(e0, e1);
                EL[w] = packsplit_lo(e0, e1);
            }
        }
        __syncthreads();
#pragma unroll
        for (int ks = 0; ks < 2; ks++) {
            uint32_t bh[4][2], bl[4][2];
#pragma unroll
            for (int p = 0; p < 2; p++) {
                int j = wn + (2 * p + bsel) * 8 + brow;
                uint32_t off = (uint32_t)(j * 16 + (((ks * 2 + bchk) ^ bswz) << 2)) * 4;
                uint32_t r[4];
                ldsm4(r, shEH + off);
                bh[2 * p][0] = r[0]; bh[2 * p][1] = r[1];
                bh[2 * p + 1][0] = r[2]; bh[2 * p + 1][1] = r[3];
                ldsm4(r, shEL + off);
                bl[2 * p][0] = r[0]; bl[2 * p][1] = r[1];
                bl[2 * p + 1][0] = r[2]; bl[2 * p + 1][1] = r[3];
            }
#pragma unroll
            for (int mt = 0; mt < 4; mt++) {
                int row = wm + mt * 16 + arow;
                uint32_t off = (uint32_t)(row * 16 + (((ks * 2 + achk) ^ aswz) << 2)) * 4;
                uint32_t ah[4], al[4];
                ldsm4(ah, shXH + off);
                ldsm4(al, shXL + off);
#pragma unroll
                for (int nt = 0; nt < 4; nt++) {
                    mma16816(acc[mt][nt], ah, bh[nt]);
                    mma16816(acc[mt][nt], ah, bl[nt]);
                    mma16816(acc[mt][nt], al, bh[nt]);
                }
            }
        }
        __syncthreads();
    }
    float* Out = (isBt ? g_Bt : g_A) + (size_t)b * DD * NN;
#pragma unroll
    for (int mt = 0; mt < 4; mt++) {
#pragma unroll
        for (int nt = 0; nt < 4; nt++) {
            float* cfr = acc[mt][nt];
            int r0 = wm + mt * 16 + g;
            int col = n0 + wn + nt * 8 + t4 * 2;
            *(float2*)(Out + (size_t)r0 * NN + col)       = make_float2(cfr[0], cfr[1]);
            *(float2*)(Out + (size_t)(r0 + 8) * NN + col) = make_float2(cfr[2], cfr[3]);
        }
    }
}

// ---- stage 5: concat + dropout ----
__device__ __forceinline__ void write_drop4(float* p, size_t idx, float4 v) {
    float4 o;
    o.x = dropscale((uint32_t)(idx + 0), v.x);
    o.y = dropscale((uint32_t)(idx + 1), v.y);
    o.z = dropscale((uint32_t)(idx + 2), v.z);
    o.w = dropscale((uint32_t)(idx + 3), v.w);
    *(float4*)p = o;
}
__global__ __launch_bounds__(256) void epilogue_kernel(const float* __restrict__ C,
                                                       float* __restrict__ out) {
    unsigned gi = blockIdx.x * 256u + threadIdx.x;
    unsigned t = gi & 511u, bd = gi >> 9, d = bd & 127u, b = bd >> 7, n = t * 4u;
    size_t src = ((size_t)(b * DD + d)) * NN + n;
    float4 c = *(const float4*)(C + src);
    float4 a = *(const float4*)(g_A + src);
    float4 bt = *(const float4*)(g_Bt + src);
    float4 ca = make_float4(c.x * a.x, c.y * a.y, c.z * a.z, c.w * a.w);
    float4 cbt = make_float4(c.x * bt.x, c.y * bt.y, c.z * bt.z, c.w * bt.w);
    size_t o0 = ((size_t)b * 4 * DD + d) * NN + n;
    const size_t st = (size_t)DD * NN;
    write_drop4(out + o0, o0, c);
    write_drop4(out + o0 + st, o0 + st, a);
    write_drop4(out + o0 + 2 * st, o0 + 2 * st, ca);
    write_drop4(out + o0 + 3 * st, o0 + 3 * st, cbt);
}

// ---- launch ----
#define MMA_SMEM (512 + 4 * 8192)
extern "C" void kernel_launch(void* const* d_in, const int* in_sizes, int n_in,
                              void* d_out, int out_size) {
    const float* C = (const float*)d_in[0];
    const float* Q = (const float*)d_in[1];
    const float* W = (const float*)d_in[2];
    float* out = (float*)d_out;
    cudaFuncSetAttribute(s_mma, cudaFuncAttributeMaxDynamicSharedMemorySize, G1_SMEM);
    bias_kernel<<<dim3(MM / 256, BB, 2), 256>>>(C, Q, W);
    split_cq_kernel<<<dim3((BB * DD * NN / 4) / 256, 2), 256>>>(C, Q);
    tsplit_kernel<<<dim3(NN / 32, DD / 32, BB * 2), 256>>>(C, Q, W);
    s_mma<<<dim3(MM / 128, NN / 128, BB), 256, G1_SMEM>>>();
    rowcombine_kernel<<<dim3((BB * NN) / 256), 256>>>();
    colcombine_kernel<<<dim3((BB * MM) / 256), 256>>>();
    cb_mma<<<dim3(MM / 128, BB), 256, MMA_SMEM>>>();
    abf_mma<<<dim3(NN / 64, BB), 256, ABF_SMEM>>>();
    epilogue_kernel<<<dim3((BB * DD * NN / 4) / 256), 256>>>(C, out);
}

// round 14
// speedup vs baseline: 1.0888x; 1.0888x over previous
#include <cuda_runtime.h>
#include <cuda_bf16.h>
#include <cstdint>
#include <cstddef>

#define BB 24
#define DD 128
#define NN 2048
#define MM 2048
#define KB 32
#define T_WORDS 2048

__device__ float g_S [(size_t)BB * NN * MM];
__device__ float g_A [(size_t)BB * DD * NN];
__device__ float g_Bt[(size_t)BB * DD * NN];
__device__ float g_L1[BB * NN];
__device__ float g_L2[BB * MM];
__device__ float g_sq[BB * MM];
__device__ float g_sc[BB * NN];
__device__ float2 g_rowp[(size_t)BB * 16 * NN];
__device__ float2 g_colp[(size_t)BB * 16 * MM];
__device__ __nv_bfloat16 g_Chi[(size_t)BB * DD * NN];
__device__ __nv_bfloat16 g_Clo[(size_t)BB * DD * NN];
__device__ __nv_bfloat16 g_Qhi[(size_t)BB * DD * MM];
__device__ __nv_bfloat16 g_Qlo[(size_t)BB * DD * MM];
__device__ __nv_bfloat16 g_CBhi[(size_t)BB * DD * MM];
__device__ __nv_bfloat16 g_CBlo[(size_t)BB * DD * MM];
__device__ __nv_bfloat16 g_CThi[(size_t)BB * NN * DD];
__device__ __nv_bfloat16 g_CTlo[(size_t)BB * NN * DD];
__device__ __nv_bfloat16 g_QWhi[(size_t)BB * MM * DD];
__device__ __nv_bfloat16 g_QWlo[(size_t)BB * MM * DD];

// ---- warp mma + ldmatrix ----
__device__ __forceinline__ void mma16816(float* c, const uint32_t* a, const uint32_t* b) {
    asm volatile("mma.sync.aligned.m16n8k16.row.col.f32.bf16.bf16.f32 "
                 "{%0,%1,%2,%3},{%4,%5,%6,%7},{%8,%9},{%0,%1,%2,%3};"
                 : "+f"(c[0]), "+f"(c[1]), "+f"(c[2]), "+f"(c[3])
                 : "r"(a[0]), "r"(a[1]), "r"(a[2]), "r"(a[3]), "r"(b[0]), "r"(b[1]));
}
__device__ __forceinline__ void ldsm4(uint32_t* r, uint32_t saddr) {
    asm volatile("ldmatrix.sync.aligned.m8n8.x4.shared.b16 {%0,%1,%2,%3}, [%4];"
                 : "=r"(r[0]), "=r"(r[1]), "=r"(r[2]), "=r"(r[3]) : "r"(saddr));
}
__device__ __forceinline__ uint32_t su32(const void* p) { return (uint32_t)__cvta_generic_to_shared(p); }

// 3-term emulated MMA over 4 n-tiles: term-major order breaks acc RAW chains;
// per-acc accumulation order stays hh, hl, lh (bit-identical results).
__device__ __forceinline__ void mma3x4(float (*acc)[4], const uint32_t* ah, const uint32_t* al,
                                       uint32_t bh[4][2], uint32_t bl[4][2]) {
#pragma unroll
    for (int nt = 0; nt < 4; nt++) mma16816(acc[nt], ah, bh[nt]);
#pragma unroll
    for (int nt = 0; nt < 4; nt++) mma16816(acc[nt], ah, bl[nt]);
#pragma unroll
    for (int nt = 0; nt < 4; nt++) mma16816(acc[nt], al, bh[nt]);
}

__device__ __forceinline__ void splitf(float x, uint16_t& h, uint16_t& l) {
    __nv_bfloat16 bh = __float2bfloat16_rn(x);
    float r = x - __bfloat162float(bh);
    __nv_bfloat16 bl = __float2bfloat16_rn(r);
    h = __bfloat16_as_ushort(bh); l = __bfloat16_as_ushort(bl);
}
__device__ __forceinline__ uint32_t packsplit_hi(float a, float b) {
    uint16_t h0, l0, h1, l1; splitf(a, h0, l0); splitf(b, h1, l1);
    return (uint32_t)h0 | ((uint32_t)h1 << 16);
}
__device__ __forceinline__ uint32_t packsplit_lo(float a, float b) {
    uint16_t h0, l0, h1, l1; splitf(a, h0, l0); splitf(b, h1, l1);
    return (uint32_t)l0 | ((uint32_t)l1 << 16);
}
// fast exp on FMA pipe (rel err ~2.4e-6)
__device__ __forceinline__ float fexp(float x) {
    float t = fmaxf(x * 1.4426950408889634f, -126.0f);
    float kf = t + 12582912.0f;
    float fi = kf - 12582912.0f;
    float f = t - fi;
    float p = 1.3333558146e-3f;
    p = fmaf(p, f, 9.6181291076e-3f);
    p = fmaf(p, f, 5.5504108665e-2f);
    p = fmaf(p, f, 2.4022650696e-1f);
    p = fmaf(p, f, 6.9314718056e-1f);
    p = fmaf(p, f, 1.0f);
    return __int_as_float(__float_as_int(p) + (((int)fi) << 23));
}

// ---- threefry2x32, JAX partitionable, key=(0,42) ----
__device__ __forceinline__ uint32_t rotl32(uint32_t x, int r) { return __funnelshift_l(x, x, r); }
#define TF_ROUND4(a, b, c, d)                       \
    x0 += x1; x1 = rotl32(x1, a); x1 ^= x0;         \
    x0 += x1; x1 = rotl32(x1, b); x1 ^= x0;         \
    x0 += x1; x1 = rotl32(x1, c); x1 ^= x0;         \
    x0 += x1; x1 = rotl32(x1, d); x1 ^= x0;
__device__ __forceinline__ uint32_t threefry_bits(uint32_t idx) {
    const uint32_t ks0 = 0u, ks1 = 42u;
    const uint32_t ks2 = 0x1BD11BDAu ^ ks0 ^ ks1;
    uint32_t x0 = 0u + ks0, x1 = idx + ks1;
    TF_ROUND4(13, 15, 26, 6)  x0 += ks1; x1 += ks2 + 1u;
    TF_ROUND4(17, 29, 16, 24) x0 += ks2; x1 += ks0 + 2u;
    TF_ROUND4(13, 15, 26, 6)  x0 += ks0; x1 += ks1 + 3u;
    TF_ROUND4(17, 29, 16, 24) x0 += ks1; x1 += ks2 + 4u;
    TF_ROUND4(13, 15, 26, 6)  x0 += ks2; x1 += ks0 + 5u;
    return x0 ^ x1;
}
__device__ __forceinline__ float dropscale(uint32_t idx, float v) {
    uint32_t bits = threefry_bits(idx);
    float u = __uint_as_float((bits >> 9) | 0x3f800000u) - 1.0f;
    return (u < 0.9f) ? v * (1.0f / 0.9f) : 0.0f;
}

// ---- stage 0: biases ----
__global__ __launch_bounds__(256) void bias_kernel(const float* __restrict__ C,
                                                   const float* __restrict__ Q,
                                                   const float* __restrict__ W) {
    int b = blockIdx.y;
    int m = blockIdx.x * 256 + threadIdx.x;
    const float* X; const float* wv; float* out;
    if (blockIdx.z == 0) { X = Q + (size_t)b * DD * MM; wv = W + b * 3 * DD;      out = g_sq + b * MM; }
    else                 { X = C + (size_t)b * DD * NN; wv = W + b * 3 * DD + DD; out = g_sc + b * NN; }
    __shared__ float ws[DD];
    if (threadIdx.x < DD) ws[threadIdx.x] = wv[threadIdx.x];
    __syncthreads();
    float acc = 0.0f;
#pragma unroll 8
    for (int d = 0; d < DD; d++) acc = fmaf(ws[d], X[(size_t)d * MM + m], acc);
    out[m] = acc;
}

// ---- stage 0b: split C,Q in [d][*] layout ----
__global__ __launch_bounds__(256) void split_cq_kernel(const float* __restrict__ C,
                                                       const float* __restrict__ Q) {
    size_t i = ((size_t)blockIdx.x * 256 + threadIdx.x) * 4;
    const float* src; __nv_bfloat16 *dh, *dl;
    if (blockIdx.y == 0) { src = C; dh = g_Chi; dl = g_Clo; }
    else                 { src = Q; dh = g_Qhi; dl = g_Qlo; }
    float4 v = *(const float4*)(src + i);
    *(uint2*)(dh + i) = make_uint2(packsplit_hi(v.x, v.y), packsplit_hi(v.z, v.w));
    *(uint2*)(dl + i) = make_uint2(packsplit_lo(v.x, v.y), packsplit_lo(v.z, v.w));
}

// ---- stage 0c: transpose-split for s_mma ----
__global__ __launch_bounds__(256) void tsplit_kernel(const float* __restrict__ C,
                                                     const float* __restrict__ Q,
                                                     const float* __restrict__ W) {
    __shared__ float ts[32][33];
    __shared__ float wsc[32];
    int z = blockIdx.z, b = z >> 1, isQ = z & 1;
    int n0 = blockIdx.x * 32, d0 = blockIdx.y * 32;
    const float* X = (isQ ? Q : C) + (size_t)b * DD * NN;
    int t = threadIdx.x, nl = t & 31, dr = t >> 5;
    if (t < 32) wsc[t] = isQ ? W[b * 3 * DD + 2 * DD + d0 + t] : 1.0f;
#pragma unroll
    for (int k = 0; k < 4; k++)
        ts[dr + k * 8][nl] = X[(size_t)(d0 + dr + k * 8) * NN + n0 + nl];
    __syncthreads();
    int nr = t >> 3, dg = (t & 7) * 4;
    __nv_bfloat16* dh = (isQ ? g_QWhi : g_CThi) + ((size_t)b * NN + n0 + nr) * DD + d0 + dg;
    __nv_bfloat16* dl = (isQ ? g_QWlo : g_CTlo) + ((size_t)b * NN + n0 + nr) * DD + d0 + dg;
    float v0 = ts[dg][nr] * wsc[dg],     v1 = ts[dg + 1][nr] * wsc[dg + 1];
    float v2 = ts[dg + 2][nr] * wsc[dg + 2], v3 = ts[dg + 3][nr] * wsc[dg + 3];
    *(uint2*)dh = make_uint2(packsplit_hi(v0, v1), packsplit_hi(v2, v3));
    *(uint2*)dl = make_uint2(packsplit_lo(v0, v1), packsplit_lo(v2, v3));
}

// ---- stage 1: S = CT * QW^T via HMMA + biases + fused stats (R11 layout) ----
#define G1_SMEM (1024 + 4 * 8192)
__global__ __launch_bounds__(256) void s_mma() {
    extern __shared__ char smc[];
    float* sc_s = (float*)smc;
    float* sq_s = (float*)(smc + 512);
    uint32_t* AH = (uint32_t*)(smc + 1024);
    uint32_t* AL = AH + T_WORDS;
    uint32_t* BH = AL + T_WORDS;
    uint32_t* BL = BH + T_WORDS;
    float* st  = (float*)(smc + 1024);
    float* rm4 = st;
    float* rfin = st + 512;
    float* rs4 = st + 640;
    float* cm2 = st + 1152;
    float* cfin = st + 1408;
    float* cs2 = st + 1536;
    int tid = threadIdx.x, lane = tid & 31, wid = tid >> 5;
    int b = blockIdx.z, n0 = blockIdx.y * 128, m0 = blockIdx.x * 128;
    if (tid < 128) { sc_s[tid] = g_sc[b * NN + n0 + tid]; sq_s[tid] = g_sq[b * MM + m0 + tid]; }
    const __nv_bfloat16* Ahg = g_CThi + ((size_t)b * NN + n0) * DD;
    const __nv_bfloat16* Alg = g_CTlo + ((size_t)b * NN + n0) * DD;
    const __nv_bfloat16* Bhg = g_QWhi + ((size_t)b * MM + m0) * DD;
    const __nv_bfloat16* Blg = g_QWlo + ((size_t)b * MM + m0) * DD;
    int wm = (wid & 1) * 64, wn = (wid >> 1) * 32;
    int g = lane >> 2, t4 = lane & 3;
    int arow = lane & 15, achk = lane >> 4, aswz = (arow >> 1) & 3;
    int brow = lane & 7, bsel = (lane >> 4) & 1, bchk = (lane >> 3) & 1, bswz = (brow >> 1) & 3;
    uint32_t shAH = su32(AH), shAL = su32(AL), shBH = su32(BH), shBL = su32(BL);
    float acc[4][4][4] = {};
    int ar = tid >> 1, ac = (tid & 1) * 2, asw = (ar >> 1) & 3;
    __syncthreads();
    for (int c = 0; c < 4; c++) {
        const uint4* pah = (const uint4*)(Ahg + (size_t)ar * DD + c * 32);
        const uint4* pal = (const uint4*)(Alg + (size_t)ar * DD + c * 32);
        const uint4* pbh = (const uint4*)(Bhg + (size_t)ar * DD + c * 32);
        const uint4* pbl = (const uint4*)(Blg + (size_t)ar * DD + c * 32);
        ((uint4*)AH)[ar * 4 + (ac ^ asw)]       = pah[ac];
        ((uint4*)AH)[ar * 4 + ((ac + 1) ^ asw)] = pah[ac + 1];
        ((uint4*)AL)[ar * 4 + (ac ^ asw)]       = pal[ac];
        ((uint4*)AL)[ar * 4 + ((ac + 1) ^ asw)] = pal[ac + 1];
        ((uint4*)BH)[ar * 4 + (ac ^ asw)]       = pbh[ac];
        ((uint4*)BH)[ar * 4 + ((ac + 1) ^ asw)] = pbh[ac + 1];
        ((uint4*)BL)[ar * 4 + (ac ^ asw)]       = pbl[ac];
        ((uint4*)BL)[ar * 4 + ((ac + 1) ^ asw)] = pbl[ac + 1];
        __syncthreads();
#pragma unroll
        for (int ks = 0; ks < 2; ks++) {
            uint32_t bh[4][2], bl[4][2];
#pragma unroll
            for (int p = 0; p < 2; p++) {
                int j = wn + (2 * p + bsel) * 8 + brow;
                uint32_t off = (uint32_t)(j * 16 + (((ks * 2 + bchk) ^ bswz) << 2)) * 4;
                uint32_t r[4];
                ldsm4(r, shBH + off);
                bh[2 * p][0] = r[0]; bh[2 * p][1] = r[1];
                bh[2 * p + 1][0] = r[2]; bh[2 * p + 1][1] = r[3];
                ldsm4(r, shBL + off);
                bl[2 * p][0] = r[0]; bl[2 * p][1] = r[1];
                bl[2 * p + 1][0] = r[2]; bl[2 * p + 1][1] = r[3];
            }
#pragma unroll
            for (int mt = 0; mt < 4; mt++) {
                int row = wm + mt * 16 + arow;
                uint32_t off = (uint32_t)(row * 16 + (((ks * 2 + achk) ^ aswz) << 2)) * 4;
                uint32_t ah[4], al[4];
                ldsm4(ah, shAH + off);
                ldsm4(al, shAL + off);
                mma3x4(acc[mt], ah, al, bh, bl);
            }
        }
        __syncthreads();
    }
    float* Sb = g_S + (size_t)b * NN * MM;
#pragma unroll
    for (int mt = 0; mt < 4; mt++) {
#pragma unroll
        for (int nt = 0; nt < 4; nt++) {
            int r0 = wm + mt * 16 + g, c0 = wn + nt * 8 + t4 * 2;
            acc[mt][nt][0] += sc_s[r0] + sq_s[c0];
            acc[mt][nt][1] += sc_s[r0] + sq_s[c0 + 1];
            acc[mt][nt][2] += sc_s[r0 + 8] + sq_s[c0];
            acc[mt][nt][3] += sc_s[r0 + 8] + sq_s[c0 + 1];
            *(float2*)(Sb + (size_t)(n0 + r0) * MM + m0 + c0)     = make_float2(acc[mt][nt][0], acc[mt][nt][1]);
            *(float2*)(Sb + (size_t)(n0 + r0 + 8) * MM + m0 + c0) = make_float2(acc[mt][nt][2], acc[mt][nt][3]);
        }
    }
#pragma unroll
    for (int mt = 0; mt < 4; mt++) {
#pragma unroll
        for (int h = 0; h < 2; h++) {
            float m = acc[mt][0][h * 2];
#pragma unroll
            for (int nt = 0; nt < 4; nt++) {
                m = fmaxf(m, acc[mt][nt][h * 2]);
                m = fmaxf(m, acc[mt][nt][h * 2 + 1]);
            }
            m = fmaxf(m, __shfl_xor_sync(0xffffffffu, m, 1));
            m = fmaxf(m, __shfl_xor_sync(0xffffffffu, m, 2));
            if (t4 == 0) rm4[(wid >> 1) * 128 + wm + mt * 16 + g + 8 * h] = m;
        }
    }
    __syncthreads();
    if (tid < 128)
        rfin[tid] = fmaxf(fmaxf(rm4[tid], rm4[128 + tid]), fmaxf(rm4[256 + tid], rm4[384 + tid]));
    __syncthreads();
#pragma unroll
    for (int mt = 0; mt < 4; mt++) {
#pragma unroll
        for (int h = 0; h < 2; h++) {
            int r = wm + mt * 16 + g + 8 * h;
            float L = rfin[r], s = 0.0f;
#pragma unroll
            for (int nt = 0; nt < 4; nt++)
                s += fexp(acc[mt][nt][h * 2] - L) + fexp(acc[mt][nt][h * 2 + 1] - L);
            s += __shfl_xor_sync(0xffffffffu, s, 1);
            s += __shfl_xor_sync(0xffffffffu, s, 2);
            if (t4 == 0) rs4[(wid >> 1) * 128 + r] = s;
        }
    }
    __syncthreads();
    if (tid < 128)
        g_rowp[((size_t)(b * 16 + (m0 >> 7))) * NN + n0 + tid] =
            make_float2(rfin[tid], rs4[tid] + rs4[128 + tid] + rs4[256 + tid] + rs4[384 + tid]);
#pragma unroll
    for (int nt = 0; nt < 4; nt++) {
#pragma unroll
        for (int e = 0; e < 2; e++) {
            float m = acc[0][nt][e];
#pragma unroll
            for (int mt = 0; mt < 4; mt++) {
                m = fmaxf(m, acc[mt][nt][e]);
                m = fmaxf(m, acc[mt][nt][2 + e]);
            }
            m = fmaxf(m, __shfl_xor_sync(0xffffffffu, m, 4));
            m = fmaxf(m, __shfl_xor_sync(0xffffffffu, m, 8));
            m = fmaxf(m, __shfl_xor_sync(0xffffffffu, m, 16));
            if (g == 0) cm2[(wid & 1) * 128 + wn + nt * 8 + t4 * 2 + e] = m;
        }
    }
    __syncthreads();
    if (tid < 128) cfin[tid] = fmaxf(cm2[tid], cm2[128 + tid]);
    __syncthreads();
#pragma unroll
    for (int nt = 0; nt < 4; nt++) {
#pragma unroll
        for (int e = 0; e < 2; e++) {
            int c = wn + nt * 8 + t4 * 2 + e;
            float L = cfin[c], s = 0.0f;
#pragma unroll
            for (int mt = 0; mt < 4; mt++)
                s += fexp(acc[mt][nt][e] - L) + fexp(acc[mt][nt][2 + e] - L);
            s += __shfl_xor_sync(0xffffffffu, s, 4);
            s += __shfl_xor_sync(0xffffffffu, s, 8);
            s += __shfl_xor_sync(0xffffffffu, s, 16);
            if (g == 0) cs2[(wid & 1) * 128 + c] = s;
        }
    }
    __syncthreads();
    if (tid < 128)
        g_colp[((size_t)(b * 16 + (n0 >> 7))) * MM + m0 + tid] =
            make_float2(cfin[tid], cs2[tid] + cs2[128 + tid]);
}

// ---- stage 2: combines ----
__global__ __launch_bounds__(256) void rowcombine_kernel() {
    int idx = blockIdx.x * 256 + threadIdx.x;
    int b = idx >> 11, n = idx & (NN - 1);
    const float2* p = g_rowp + (size_t)(b * 16) * NN + n;
    float2 f = p[0]; float mx = f.x, s = f.y;
#pragma unroll
    for (int t = 1; t < 16; t++) {
        float2 g = p[(size_t)t * NN];
        float nm = fmaxf(mx, g.x);
        s = s * __expf(mx - nm) + g.y * __expf(g.x - nm); mx = nm;
    }
    g_L1[idx] = mx + logf(s);
}
__global__ __launch_bounds__(256) void colcombine_kernel() {
    int idx = blockIdx.x * 256 + threadIdx.x;
    int b = idx >> 11, m = idx & (MM - 1);
    const float2* p = g_colp + (size_t)(b * 16) * MM + m;
    float2 f = p[0]; float mx = f.x, s = f.y;
#pragma unroll
    for (int t = 1; t < 16; t++) {
        float2 g = p[(size_t)t * MM];
        float nm = fmaxf(mx, g.x);
        s = s * __expf(mx - nm) + g.y * __expf(g.x - nm); mx = nm;
    }
    g_L2[idx] = mx + logf(s);
}

// ---- stage 3: CB = C * E2 via HMMA (R11 single-buffer) ----
__global__ __launch_bounds__(256) void cb_mma() {
    extern __shared__ char smc[];
    float* l2s = (float*)smc;
    uint32_t* AH = (uint32_t*)(smc + 512);
    uint32_t* AL = AH + T_WORDS;
    uint32_t* EH = AL + T_WORDS;
    uint32_t* EL = EH + T_WORDS;
    int tid = threadIdx.x, lane = tid & 31, wid = tid >> 5;
    int b = blockIdx.y, m0 = blockIdx.x * 128;
    if (tid < 128) l2s[tid] = g_L2[b * MM + m0 + tid];
    const float* Sb = g_S + (size_t)b * NN * MM;
    const __nv_bfloat16* Ch = g_Chi + (size_t)b * DD * NN;
    const __nv_bfloat16* Cl = g_Clo + (size_t)b * DD * NN;
    int wm = (wid & 1) * 64, wn = (wid >> 1) * 32;
    int g = lane >> 2, t4 = lane & 3;
    int arow = lane & 15, achk = lane >> 4, aswz = (arow >> 1) & 3;
    int brow = lane & 7, bsel = (lane >> 4) & 1, bchk = (lane >> 3) & 1, bswz = (brow >> 1) & 3;
    uint32_t shAH = su32(AH), shAL = su32(AL), shEH = su32(EH), shEL = su32(EL);
    float acc[4][4][4] = {};
    int ar = tid >> 1, ac = (tid & 1) * 2, asw = (ar >> 1) & 3;
    int kp = tid & 15, mb = tid >> 4;
    __syncthreads();
    for (int c = 0; c < NN / KB; c++) {
        int n0 = c * KB;
        {
            const uint4* ph = (const uint4*)(Ch + (size_t)ar * NN + n0);
            const uint4* pl = (const uint4*)(Cl + (size_t)ar * NN + n0);
            ((uint4*)AH)[ar * 4 + (ac ^ asw)]       = ph[ac];
            ((uint4*)AH)[ar * 4 + ((ac + 1) ^ asw)] = ph[ac + 1];
            ((uint4*)AL)[ar * 4 + (ac ^ asw)]       = pl[ac];
            ((uint4*)AL)[ar * 4 + ((ac + 1) ^ asw)] = pl[ac + 1];
        }
        {
            const float* s0 = Sb + (size_t)(n0 + 2 * kp) * MM + m0 + mb * 8;
            const float* s1 = s0 + MM;
            float4 x0 = *(const float4*)s0, x1 = *(const float4*)(s0 + 4);
            float4 y0 = *(const float4*)s1, y1 = *(const float4*)(s1 + 4);
            float xs[8] = {x0.x, x0.y, x0.z, x0.w, x1.x, x1.y, x1.z, x1.w};
            float ys[8] = {y0.x, y0.y, y0.z, y0.w, y1.x, y1.y, y1.z, y1.w};
#pragma unroll
            for (int i = 0; i < 8; i++) {
                int m = mb * 8 + i;
                float L = l2s[m];
                float e0 = fexp(xs[i] - L), e1 = fexp(ys[i] - L);
                int w = m * 16 + (kp ^ (((m >> 1) & 3) << 2));
                EH[w] = packsplit_hi(e0, e1);
                EL[w] = packsplit_lo(e0, e1);
            }
        }
        __syncthreads();
#pragma unroll
        for (int ks = 0; ks < 2; ks++) {
            uint32_t bh[4][2], bl[4][2];
#pragma unroll
            for (int p = 0; p < 2; p++) {
                int j = wn + (2 * p + bsel) * 8 + brow;
                uint32_t off = (uint32_t)(j * 16 + (((ks * 2 + bchk) ^ bswz) << 2)) * 4;
                uint32_t r[4];
                ldsm4(r, shEH + off);
                bh[2 * p][0] = r[0]; bh[2 * p][1] = r[1];
                bh[2 * p + 1][0] = r[2]; bh[2 * p + 1][1] = r[3];
                ldsm4(r, shEL + off);
                bl[2 * p][0] = r[0]; bl[2 * p][1] = r[1];
                bl[2 * p + 1][0] = r[2]; bl[2 * p + 1][1] = r[3];
            }
#pragma unroll
            for (int mt = 0; mt < 4; mt++) {
                int row = wm + mt * 16 + arow;
                uint32_t off = (uint32_t)(row * 16 + (((ks * 2 + achk) ^ aswz) << 2)) * 4;
                uint32_t ah[4], al[4];
                ldsm4(ah, shAH + off);
                ldsm4(al, shAL + off);
                mma3x4(acc[mt], ah, al, bh, bl);
            }
        }
        __syncthreads();
    }
#pragma unroll
    for (int mt = 0; mt < 4; mt++) {
#pragma unroll
        for (int nt = 0; nt < 4; nt++) {
            float* cfr = acc[mt][nt];
            int d0 = wm + mt * 16 + g;
            int col = m0 + wn + nt * 8 + t4 * 2;
            size_t o0 = (size_t)(b * DD + d0) * MM + col;
            size_t o1 = (size_t)(b * DD + d0 + 8) * MM + col;
            *(uint32_t*)(g_CBhi + o0) = packsplit_hi(cfr[0], cfr[1]);
            *(uint32_t*)(g_CBlo + o0) = packsplit_lo(cfr[0], cfr[1]);
            *(uint32_t*)(g_CBhi + o1) = packsplit_hi(cfr[2], cfr[3]);
            *(uint32_t*)(g_CBlo + o1) = packsplit_lo(cfr[2], cfr[3]);
        }
    }
}

// ---- stage 4: fused A + Bt (R11 single-buffer) ----
#define ABF_SMEM (512 + 4 * 8192 + 2 * 4096)
__global__ __launch_bounds__(256) void abf_mma() {
    extern __shared__ char smc[];
    float* l1s = (float*)smc;
    uint32_t* QH = (uint32_t*)(smc + 512);
    uint32_t* QL = QH + 2048;
    uint32_t* BH = QL + 2048;
    uint32_t* BL = BH + 2048;
    uint32_t* EH = BL + 2048;
    uint32_t* EL = EH + 1024;
    int tid = threadIdx.x, lane = tid & 31, wid = tid >> 5;
    int b = blockIdx.y, n0 = blockIdx.x * 64;
    if (tid < 64) l1s[tid] = g_L1[b * NN + n0 + tid];
    const float* Sb = g_S + (size_t)b * NN * MM;
    const __nv_bfloat16* Qh = g_Qhi + (size_t)b * DD * MM;
    const __nv_bfloat16* Ql = g_Qlo + (size_t)b * DD * MM;
    const __nv_bfloat16* Bh = g_CBhi + (size_t)b * DD * MM;
    const __nv_bfloat16* Bl = g_CBlo + (size_t)b * DD * MM;
    int isBt = wid >> 2, wg = wid & 3;
    int wm = (wg & 1) * 64, wn = (wg >> 1) * 32;
    int g = lane >> 2, t4 = lane & 3;
    int arow = lane & 15, achk = lane >> 4, aswz = (arow >> 1) & 3;
    int brow = lane & 7, bsel = (lane >> 4) & 1, bchk = (lane >> 3) & 1, bswz = (brow >> 1) & 3;
    uint32_t shXH = isBt ? su32(BH) : su32(QH);
    uint32_t shXL = isBt ? su32(BL) : su32(QL);
    uint32_t shEH = su32(EH), shEL = su32(EL);
    float acc[4][4][4] = {};
    int ar = tid >> 1, ac = (tid & 1) * 2, asw = (ar >> 1) & 3;
    int nr = tid >> 2, q4 = tid & 3;
    __syncthreads();
    for (int c = 0; c < MM / KB; c++) {
        int mc0 = c * KB;
        {
            const uint4* pqh = (const uint4*)(Qh + (size_t)ar * MM + mc0);
            const uint4* pql = (const uint4*)(Ql + (size_t)ar * MM + mc0);
            const uint4* pbh = (const uint4*)(Bh + (size_t)ar * MM + mc0);
            const uint4* pbl = (const uint4*)(Bl + (size_t)ar * MM + mc0);
            ((uint4*)QH)[ar * 4 + (ac ^ asw)]       = pqh[ac];
            ((uint4*)QH)[ar * 4 + ((ac + 1) ^ asw)] = pqh[ac + 1];
            ((uint4*)QL)[ar * 4 + (ac ^ asw)]       = pql[ac];
            ((uint4*)QL)[ar * 4 + ((ac + 1) ^ asw)] = pql[ac + 1];
            ((uint4*)BH)[ar * 4 + (ac ^ asw)]       = pbh[ac];
            ((uint4*)BH)[ar * 4 + ((ac + 1) ^ asw)] = pbh[ac + 1];
            ((uint4*)BL)[ar * 4 + (ac ^ asw)]       = pbl[ac];
            ((uint4*)BL)[ar * 4 + ((ac + 1) ^ asw)] = pbl[ac + 1];
        }
        {
            const float* sp = Sb + (size_t)(n0 + nr) * MM + mc0 + q4 * 8;
            float4 v0 = *(const float4*)sp, v1 = *(const float4*)(sp + 4);
            float vs[8] = {v0.x, v0.y, v0.z, v0.w, v1.x, v1.y, v1.z, v1.w};
            float L = l1s[nr];
            int sn = ((nr >> 1) & 3) << 2;
#pragma unroll
            for (int j = 0; j < 4; j++) {
                float e0 = fexp(vs[2 * j] - L), e1 = fexp(vs[2 * j + 1] - L);
                int w = nr * 16 + ((q4 * 4 + j) ^ sn);
                EH[w] = packsplit_hi(e0, e1);
                EL[w] = packsplit_lo(e0, e1);
            }
        }
        __syncthreads();
#pragma unroll
        for (int ks = 0; ks < 2; ks++) {
            uint32_t bh[4][2], bl[4][2];
#pragma unroll
            for (int p = 0; p < 2; p++) {
                int j = wn + (2 * p + bsel) * 8 + brow;
                uint32_t off = (uint32_t)(j * 16 + (((ks * 2 + bchk) ^ bswz) << 2)) * 4;
                uint32_t r[4];
                ldsm4(r, shEH + off);
                bh[2 * p][0] = r[0]; bh[2 * p][1] = r[1];
                bh[2 * p + 1][0] = r[2]; bh[2 * p + 1][1] = r[3];
                ldsm4(r, shEL + off);
                bl[2 * p][0] = r[0]; bl[2 * p][1] = r[1];
                bl[2 * p + 1][0] = r[2]; bl[2 * p + 1][1] = r[3];
            }
#pragma unroll
            for (int mt = 0; mt < 4; mt++) {
                int row = wm + mt * 16 + arow;
                uint32_t off = (uint32_t)(row * 16 + (((ks * 2 + achk) ^ aswz) << 2)) * 4;
                uint32_t ah[4], al[4];
                ldsm4(ah, shXH + off);
                ldsm4(al, shXL + off);
                mma3x4(acc[mt], ah, al, bh, bl);
            }
        }
        __syncthreads();
    }
    float* Out = (isBt ? g_Bt : g_A) + (size_t)b * DD * NN;
#pragma unroll
    for (int mt = 0; mt < 4; mt++) {
#pragma unroll
        for (int nt = 0; nt < 4; nt++) {
            float* cfr = acc[mt][nt];
            int r0 = wm + mt * 16 + g;
            int col = n0 + wn + nt * 8 + t4 * 2;
            *(float2*)(Out + (size_t)r0 * NN + col)       = make_float2(cfr[0], cfr[1]);
            *(float2*)(Out + (size_t)(r0 + 8) * NN + col) = make_float2(cfr[2], cfr[3]);
        }
    }
}

// ---- stage 5: concat + dropout ----
__device__ __forceinline__ void write_drop4(float* p, size_t idx, float4 v) {
    float4 o;
    o.x = dropscale((uint32_t)(idx + 0), v.x);
    o.y = dropscale((uint32_t)(idx + 1), v.y);
    o.z = dropscale((uint32_t)(idx + 2), v.z);
    o.w = dropscale((uint32_t)(idx + 3), v.w);
    *(float4*)p = o;
}
__global__ __launch_bounds__(256) void epilogue_kernel(const float* __restrict__ C,
                                                       float* __restrict__ out) {
    unsigned gi = blockIdx.x * 256u + threadIdx.x;
    unsigned t = gi & 511u, bd = gi >> 9, d = bd & 127u, b = bd >> 7, n = t * 4u;
    size_t src = ((size_t)(b * DD + d)) * NN + n;
    float4 c = *(const float4*)(C + src);
    float4 a = *(const float4*)(g_A + src);
    float4 bt = *(const float4*)(g_Bt + src);
    float4 ca = make_float4(c.x * a.x, c.y * a.y, c.z * a.z, c.w * a.w);
    float4 cbt = make_float4(c.x * bt.x, c.y * bt.y, c.z * bt.z, c.w * bt.w);
    size_t o0 = ((size_t)b * 4 * DD + d) * NN + n;
    const size_t st = (size_t)DD * NN;
    write_drop4(out + o0, o0, c);
    write_drop4(out + o0 + st, o0 + st, a);
    write_drop4(out + o0 + 2 * st, o0 + 2 * st, ca);
    write_drop4(out + o0 + 3 * st, o0 + 3 * st, cbt);
}

// ---- launch ----
#define MMA_SMEM (512 + 4 * 8192)
extern "C" void kernel_launch(void* const* d_in, const int* in_sizes, int n_in,
                              void* d_out, int out_size) {
    const float* C = (const float*)d_in[0];
    const float* Q = (const float*)d_in[1];
    const float* W = (const float*)d_in[2];
    float* out = (float*)d_out;
    bias_kernel<<<dim3(MM / 256, BB, 2), 256>>>(C, Q, W);
    split_cq_kernel<<<dim3((BB * DD * NN / 4) / 256, 2), 256>>>(C, Q);
    tsplit_kernel<<<dim3(NN / 32, DD / 32, BB * 2), 256>>>(C, Q, W);
    s_mma<<<dim3(MM / 128, NN / 128, BB), 256, G1_SMEM>>>();
    rowcombine_kernel<<<dim3((BB * NN) / 256), 256>>>();
    colcombine_kernel<<<dim3((BB * MM) / 256), 256>>>();
    cb_mma<<<dim3(MM / 128, BB), 256, MMA_SMEM>>>();
    abf_mma<<<dim3(NN / 64, BB), 256, ABF_SMEM>>>();
    epilogue_kernel<<<dim3((BB * DD * NN / 4) / 256), 256>>>(C, out);
}